// round 15
// baseline (speedup 1.0000x reference)
#include <cuda_runtime.h>
#include <cstdint>

#define NPTS     32768
#define KCODES   1024
#define DDIM     256
#define HWSZ     1024
#define DHW      (DDIM*HWSZ)
#define HALF_OUT 8388608
#define CMAXC    64
#define PPC      111          // points per pass1 CTA (296 x 111 >= 32768)
#define GRID1    296          // 2 CTAs/SM -> exactly one wave
#define WLCAP    4194304

typedef unsigned int u32;
typedef unsigned short u16;
typedef unsigned long long u64;

// Scratch (static __device__ — no allocations)
__device__ u32    g_c8T[KCODES * 64];   // [8 tile][64 word][128 code] packed int8
__device__ float4 g_cs4[KCODES];        // (cc exact-chain, sc=max|c|, rc=||Δc||, 0)
__device__ float  g_xT[NPTS * DDIM];    // 32MB point-major x copy
__device__ float  g_xx[NPTS];
__device__ float  g_mar[NPTS];
__device__ float  g_minq[NPTS];
__device__ u16    g_cand[NPTS * CMAXC];
__device__ float  g_cdda[NPTS * CMAXC];
__device__ u32    g_ccnt[NPTS];
__device__ u32    g_khist[KCODES];      // survivors per code
__device__ u32    g_koff[KCODES];       // scatter cursors (exclusive prefix)
__device__ u32    g_wtotal;
__device__ u32    g_wl[WLCAP];          // k-sorted worklist: (n<<10)|k
__device__ u64    g_best[NPTS];

__device__ __forceinline__ u32 smem_u32(const void* p) {
    return (u32)__cvta_generic_to_shared(p);
}
__device__ __forceinline__ void cp_async16(u32 dst, const void* src) {
    asm volatile("cp.async.cg.shared.global [%0], [%1], 16;" :: "r"(dst), "l"(src));
}
__device__ __forceinline__ void cp_commit() { asm volatile("cp.async.commit_group;"); }
__device__ __forceinline__ void cp_wait0()  { asm volatile("cp.async.wait_group 0;" ::: "memory"); }

// ---------------------------------------------------------------------------
// code_prep: one WARP per code; blocks 0..3 also zero the k-histogram.
// ---------------------------------------------------------------------------
__global__ void code_prep(const float* __restrict__ cb) {
    const int tid = threadIdx.x, lane = tid & 31, wid = tid >> 5;
    if (blockIdx.x < 4) g_khist[blockIdx.x * 256 + tid] = 0;
    const int k = blockIdx.x * 8 + wid;
    const float* row = cb + (size_t)k * DDIM;

    float4 va = *(const float4*)(row + lane * 8);
    float4 vb = *(const float4*)(row + lane * 8 + 4);
    float mx = fmaxf(fmaxf(fmaxf(fabsf(va.x), fabsf(va.y)), fmaxf(fabsf(va.z), fabsf(va.w))),
                     fmaxf(fmaxf(fabsf(vb.x), fabsf(vb.y)), fmaxf(fabsf(vb.z), fabsf(vb.w))));
    #pragma unroll
    for (int o = 16; o; o >>= 1) mx = fmaxf(mx, __shfl_xor_sync(0xFFFFFFFFu, mx, o));

    float mxx = fmaxf(mx, 1e-30f);
    float s127 = 127.0f / mxx;
    float cinv = mxx / 127.0f;

    float rsum = 0.0f;
    u32 base = (u32)(k >> 7) * 8192u + (u32)(k & 127);
    float vv[8] = {va.x, va.y, va.z, va.w, vb.x, vb.y, vb.z, vb.w};
    #pragma unroll
    for (int h = 0; h < 2; ++h) {
        u32 pk = 0;
        #pragma unroll
        for (int e = 0; e < 4; ++e) {
            float ve = vv[h * 4 + e];
            int q = __float2int_rn(ve * s127);
            q = max(-127, min(127, q));
            float diff = fmaf(-(float)q, cinv, ve);
            rsum += diff * diff;
            pk |= ((u32)(q & 0xFF)) << (8 * e);
        }
        g_c8T[base + (u32)(lane * 2 + h) * 128u] = pk;
    }
    #pragma unroll
    for (int o = 16; o; o >>= 1) rsum += __shfl_xor_sync(0xFFFFFFFFu, rsum, o);

    if (lane == 0) {
        float s = 0.0f;
        for (int d0 = 0; d0 < DDIM; d0 += 16) {
            float4 w0 = *(const float4*)(row + d0);
            float4 w1 = *(const float4*)(row + d0 + 4);
            float4 w2 = *(const float4*)(row + d0 + 8);
            float4 w3 = *(const float4*)(row + d0 + 12);
            float v[16] = {w0.x, w0.y, w0.z, w0.w, w1.x, w1.y, w1.z, w1.w,
                           w2.x, w2.y, w2.z, w2.w, w3.x, w3.y, w3.z, w3.w};
            #pragma unroll
            for (int e = 0; e < 16; ++e)
                s = __fadd_rn(s, __fmul_rn(v[e], v[e]));
        }
        g_cs4[k] = make_float4(s, mx, sqrtf(rsum) * 1.02f + 1e-7f, 0.0f);
    }
}

// ---------------------------------------------------------------------------
// Pass 1 (unchanged from R14): fused x-prep (+xT copy) + dp4a GEMM + collect.
// ---------------------------------------------------------------------------
__global__ void __launch_bounds__(512, 2)
pass1_kernel(const float* __restrict__ z) {
    extern __shared__ u32 sdyn[];   // As[8192] | Bs0[8192] | Bs1[8192] | sCS[2048]
    u32* As = sdyn;
    u32* Bsb[2] = { sdyn + 8192, sdyn + 16384 };
    float2* sCS = (float2*)(sdyn + 24576);
    __shared__ float sMar[128], sXX[128], sSX[128], sRX[128];
    __shared__ float sred[2][16];

    const int tid = threadIdx.x;
    const int tx = tid & 31;
    const int ty = tid >> 5;
    const int p0 = blockIdx.x * PPC;
    const int npts = min(PPC, NPTS - p0);

    {
        u32 db = smem_u32(Bsb[0]);
        #pragma unroll
        for (int r = 0; r < 4; ++r)
            cp_async16(db + (u32)(r * 512 + tid) * 16u, g_c8T + (r * 512 + tid) * 4);
        cp_commit();
    }

    {
        float mcc = 0.0f, mrc = 0.0f;
        #pragma unroll
        for (int l = 0; l < 2; ++l) {
            int k = tid + l * 512;
            float4 cs = g_cs4[k];
            sCS[k] = make_float2(cs.x, cs.y);
            mcc = fmaxf(mcc, cs.x);
            mrc = fmaxf(mrc, cs.z);
        }
        #pragma unroll
        for (int o = 16; o; o >>= 1) {
            mcc = fmaxf(mcc, __shfl_xor_sync(0xFFFFFFFFu, mcc, o));
            mrc = fmaxf(mrc, __shfl_xor_sync(0xFFFFFFFFu, mrc, o));
        }
        if (tx == 0) { sred[0][ty] = mcc; sred[1][ty] = mrc; }
    }

    if (tid < 128) {
        const int p = tid, n = p0 + p;
        if (p < npts) {
            const int bb = n >> 10, hw = n & 1023;
            const float* bp = z + (size_t)bb * DHW + hw;
            g_ccnt[n] = 0;
            float s = 0.0f;
            for (int d0 = 0; d0 < DDIM; d0 += 16) {
                float v[16];
                #pragma unroll
                for (int e = 0; e < 16; ++e) v[e] = bp[(size_t)(d0 + e) * HWSZ];
                #pragma unroll
                for (int e = 0; e < 16; ++e)
                    s = __fadd_rn(s, __fmul_rn(v[e], v[e]));
            }
            g_xx[n] = s;
            sXX[p] = s;
        } else {
            sXX[p] = 3.0e38f;
        }
    } else if (tid < 256) {
        const int p = tid - 128, n = p0 + p;
        if (p < npts) {
            const int bb = n >> 10, hw = n & 1023;
            const float* bp = z + (size_t)bb * DHW + hw;
            float mx = 0.0f;
            for (int d0 = 0; d0 < DDIM; d0 += 16) {
                float v[16];
                #pragma unroll
                for (int e = 0; e < 16; ++e) v[e] = bp[(size_t)(d0 + e) * HWSZ];
                #pragma unroll
                for (int e = 0; e < 16; ++e) mx = fmaxf(mx, fabsf(v[e]));
            }
            float mxx = fmaxf(mx, 1e-30f);
            float s127 = 127.0f / mxx;
            float xinv = mxx / 127.0f;
            float rsum = 0.0f;
            float* xtr = g_xT + (size_t)n * DDIM;
            #pragma unroll 4
            for (int w = 0; w < 64; ++w) {
                u32 pk = 0;
                float xe4[4];
                #pragma unroll
                for (int e = 0; e < 4; ++e) {
                    float xe = bp[(size_t)(w * 4 + e) * HWSZ];   // L2 hit
                    xe4[e] = xe;
                    int q = __float2int_rn(xe * s127);
                    q = max(-127, min(127, q));
                    float diff = fmaf(-(float)q, xinv, xe);
                    rsum += diff * diff;
                    pk |= ((u32)(q & 0xFF)) << (8 * e);
                }
                As[w * 128 + p] = pk;
                float4 xv; xv.x = xe4[0]; xv.y = xe4[1]; xv.z = xe4[2]; xv.w = xe4[3];
                *(float4*)(xtr + w * 4) = xv;
            }
            sSX[p] = mx * (1.0f / 16129.0f);
            sRX[p] = sqrtf(rsum) * 1.02f + 1e-7f;
        } else {
            #pragma unroll 8
            for (int w = 0; w < 64; ++w) As[w * 128 + p] = 0u;
            sSX[p] = 0.0f;
            sRX[p] = 0.0f;
        }
    }
    __syncthreads();

    float MCC = 0.0f, MRC = 0.0f;
    #pragma unroll
    for (int i = 0; i < 16; ++i) {
        MCC = fmaxf(MCC, sred[0][i]);
        MRC = fmaxf(MRC, sred[1][i]);
    }
    const float Smax = sqrtf(MCC);

    if (tid < 128) {
        const int p = tid;
        if (p < npts) {
            float rx = sRX[p], s = sXX[p];
            float errdot = rx * Smax + (sqrtf(s) + rx) * MRC;
            float marg = 2.5f * errdot + 2e-4f;
            sMar[p] = marg;
            g_mar[p0 + p] = marg;
        } else {
            sMar[p] = 0.0f;
        }
    }
    cp_wait0();
    __syncthreads();

    float gmin8[8];
    #pragma unroll
    for (int i = 0; i < 8; ++i) gmin8[i] = 3.0e38f;

    for (int t = 0; t < 8; ++t) {
        if (t < 7) {
            u32 db = smem_u32(Bsb[(t + 1) & 1]);
            const u32* src = g_c8T + (t + 1) * 8192;
            #pragma unroll
            for (int r = 0; r < 4; ++r)
                cp_async16(db + (u32)(r * 512 + tid) * 16u, src + (r * 512 + tid) * 4);
            cp_commit();
        }
        const uint4* Bt4 = (const uint4*)Bsb[t & 1];
        const uint4* At4 = (const uint4*)As;

        int m[32];
        #pragma unroll
        for (int i = 0; i < 32; ++i) m[i] = 0;

        #pragma unroll 4
        for (int w = 0; w < 64; ++w) {
            uint4 A0 = At4[w * 32 + ty * 2];
            uint4 A1 = At4[w * 32 + ty * 2 + 1];
            uint4 B  = Bt4[w * 32 + tx];
            int a[8] = {(int)A0.x, (int)A0.y, (int)A0.z, (int)A0.w,
                        (int)A1.x, (int)A1.y, (int)A1.z, (int)A1.w};
            int bb[4] = {(int)B.x, (int)B.y, (int)B.z, (int)B.w};
            #pragma unroll
            for (int i = 0; i < 8; ++i)
                #pragma unroll
                for (int j = 0; j < 4; ++j)
                    m[i * 4 + j] = __dp4a(a[i], bb[j], m[i * 4 + j]);
        }

        {
            float xx8[8], sx8[8], lmin8[8];
            #pragma unroll
            for (int i = 0; i < 8; ++i) {
                xx8[i] = sXX[ty * 8 + i];
                sx8[i] = sSX[ty * 8 + i];
                lmin8[i] = 3.0e38f;
            }
            #pragma unroll
            for (int j = 0; j < 4; ++j) {
                float2 cj = sCS[t * 128 + tx * 4 + j];
                #pragma unroll
                for (int i = 0; i < 8; ++i) {
                    float dd = fmaf(-2.0f * sx8[i] * cj.y,
                                    (float)m[i * 4 + j], xx8[i] + cj.x);
                    m[i * 4 + j] = __float_as_int(dd);
                    lmin8[i] = fminf(lmin8[i], dd);
                }
            }
            #pragma unroll
            for (int i = 0; i < 8; ++i) {
                float v = lmin8[i];
                #pragma unroll
                for (int o = 1; o < 32; o <<= 1)
                    v = fminf(v, __shfl_xor_sync(0xFFFFFFFFu, v, o));
                gmin8[i] = fminf(gmin8[i], v);
            }
            #pragma unroll
            for (int i = 0; i < 8; ++i) {
                int pt = ty * 8 + i;
                if (pt < npts) {
                    float thr = gmin8[i] + sMar[pt];
                    int n = p0 + pt;
                    #pragma unroll
                    for (int j = 0; j < 4; ++j) {
                        float dd = __int_as_float(m[i * 4 + j]);
                        if (dd <= thr) {
                            u32 s = atomicAdd(&g_ccnt[n], 1u);
                            if (s < CMAXC) {
                                g_cand[(size_t)n * CMAXC + s] = (u16)(t * 128 + tx * 4 + j);
                                g_cdda[(size_t)n * CMAXC + s] = dd;
                            }
                        }
                    }
                }
            }
        }
        if (t < 7) cp_wait0();
        __syncthreads();
    }
    if (tx == 0) {
        #pragma unroll
        for (int i = 0; i < 8; ++i) {
            int pt = ty * 8 + i;
            if (pt < npts) g_minq[p0 + pt] = gmin8[i];
        }
    }
}

// ---------------------------------------------------------------------------
// filter_count: per point — final-window filter with in-place compaction of
// g_cand, per-k histogram. Inits g_best.
// ---------------------------------------------------------------------------
__global__ void __launch_bounds__(256)
filter_count() {
    int n = blockIdx.x * 256 + threadIdx.x;
    g_best[n] = ~0ull;
    u32 cnt = g_ccnt[n];
    if (cnt <= CMAXC) {
        float thr = g_minq[n] + g_mar[n];
        u32 m = 0;
        for (u32 c = 0; c < cnt; ++c) {
            u16 k = g_cand[(size_t)n * CMAXC + c];
            if (g_cdda[(size_t)n * CMAXC + c] <= thr) {
                g_cand[(size_t)n * CMAXC + m] = k;   // m <= c: safe in-place
                m++;
                atomicAdd(&g_khist[k], 1u);
            }
        }
        g_ccnt[n] = m;
    } else {   // never-seen overflow: all codes
        for (int k = 0; k < KCODES; ++k) atomicAdd(&g_khist[k], 1u);
    }
}

// ---------------------------------------------------------------------------
// scan: 1 block, exclusive prefix over 1024 buckets -> g_koff, total -> g_wtotal.
// ---------------------------------------------------------------------------
__global__ void __launch_bounds__(1024)
scan_kernel() {
    __shared__ u32 buf[2][1024];
    int t = threadIdx.x;
    buf[0][t] = g_khist[t];
    __syncthreads();
    int src = 0;
    for (int o = 1; o < 1024; o <<= 1) {
        buf[1 - src][t] = (t >= o) ? buf[src][t] + buf[src][t - o] : buf[src][t];
        src = 1 - src;
        __syncthreads();
    }
    // inclusive in buf[src]; exclusive = inclusive - own
    g_koff[t] = buf[src][t] - g_khist[t];
    if (t == 1023) g_wtotal = buf[src][1023] > WLCAP ? WLCAP : buf[src][1023];
}

// ---------------------------------------------------------------------------
// scatter: per point — place survivors at per-k cursors (k-sorted worklist).
// ---------------------------------------------------------------------------
__global__ void __launch_bounds__(256)
scatter_kernel() {
    int n = blockIdx.x * 256 + threadIdx.x;
    u32 cnt = g_ccnt[n];
    if (cnt <= CMAXC) {
        for (u32 c = 0; c < cnt; ++c) {
            u32 k = g_cand[(size_t)n * CMAXC + c];
            u32 pos = atomicAdd(&g_koff[k], 1u);
            if (pos < WLCAP) g_wl[pos] = ((u32)n << 10) | k;
        }
    } else {
        for (u32 k = 0; k < KCODES; ++k) {
            u32 pos = atomicAdd(&g_koff[k], 1u);
            if (pos < WLCAP) g_wl[pos] = ((u32)n << 10) | k;
        }
    }
}

// ---------------------------------------------------------------------------
// chain: k-sorted worklist -> warp lanes mostly share k -> c-row loads are
// broadcast (1 line/instr instead of 32). Pinned bitwise chain per entry;
// winner via atomicMin on (dd_bits<<32)|k (lexicographic = jnp.argmin).
// ---------------------------------------------------------------------------
__global__ void __launch_bounds__(256)
chain_kernel(const float* __restrict__ cb) {
    u32 W = g_wtotal;
    for (u32 i = blockIdx.x * 256 + threadIdx.x; i < W; i += gridDim.x * 256) {
        u32 e = g_wl[i];
        u32 n = e >> 10;
        u32 k = e & 1023u;
        const float4* xr = (const float4*)(g_xT + (size_t)n * DDIM);
        const float4* cr = (const float4*)(cb + (size_t)k * DDIM);
        float mm = 0.0f;
        #pragma unroll 8
        for (int d4 = 0; d4 < DDIM / 4; ++d4) {
            float4 xv = xr[d4];
            float4 cv = cr[d4];
            mm = __fmaf_rn(xv.x, cv.x, mm);
            mm = __fmaf_rn(xv.y, cv.y, mm);
            mm = __fmaf_rn(xv.z, cv.z, mm);
            mm = __fmaf_rn(xv.w, cv.w, mm);
        }
        float t1 = __fadd_rn(g_xx[n], g_cs4[k].x);
        float dd = __fadd_rn(t1, -(2.0f * mm));
        u64 pack = ((u64)(u32)__float_as_int(dd) << 32) | k;
        atomicMin(&g_best[n], pack);
    }
}

// ---------------------------------------------------------------------------
// Gather + straight-through outputs (proven form, ~19.5us).
// ---------------------------------------------------------------------------
#define GPTS 32
__global__ void __launch_bounds__(256)
gather_kernel(const float* __restrict__ z, const float* __restrict__ cb,
              float* __restrict__ out) {
    __shared__ float tile[GPTS][DDIM + 1];
    __shared__ int sidx[GPTS];

    const int tid = threadIdx.x;
    const int p0 = blockIdx.x * GPTS;
    const int b = p0 >> 10;
    const int hw0 = p0 & 1023;

    if (tid < GPTS) sidx[tid] = (int)(g_best[p0 + tid] & 1023u);
    __syncthreads();

    #pragma unroll
    for (int r = 0; r < 8; ++r) {
        int lin = tid + r * 256;
        int p = lin >> 6;
        int d4 = (lin & 63) << 2;
        float4 v = *reinterpret_cast<const float4*>(cb + (size_t)sidx[p] * DDIM + d4);
        tile[p][d4 + 0] = v.x;
        tile[p][d4 + 1] = v.y;
        tile[p][d4 + 2] = v.z;
        tile[p][d4 + 3] = v.w;
    }
    __syncthreads();

    const float* zb = z + (size_t)b * DHW + hw0;
    float* o1 = out + (size_t)b * DHW + hw0;
    const int p = tid & 31;
    const int dchunk = tid >> 5;

    #pragma unroll
    for (int dd = 0; dd < DDIM; dd += 8) {
        int d = dd + dchunk;
        size_t off = (size_t)d * HWSZ + p;
        float x = zb[off];
        float q = tile[p][d];
        float t = __fadd_rn(q, -x);
        o1[off]            = __fadd_rn(x, t);
        o1[off + HALF_OUT] = q;
    }
}

// ---------------------------------------------------------------------------
extern "C" void kernel_launch(void* const* d_in, const int* in_sizes, int n_in,
                              void* d_out, int out_size) {
    const float* z  = (const float*)d_in[0];   // z_e_x  [32,256,32,32]
    const float* cb = (const float*)d_in[1];   // codebook [1024,256]
    float* out = (float*)d_out;                // [2, 32,256,32,32]

    static int inited = 0;
    if (!inited) {
        cudaFuncSetAttribute(pass1_kernel,
                             cudaFuncAttributeMaxDynamicSharedMemorySize, 106496);
        inited = 1;
    }

    code_prep<<<128, 256>>>(cb);              // 1 (also zeroes khist)
    pass1_kernel<<<GRID1, 512, 106496>>>(z);  // 2
    filter_count<<<NPTS / 256, 256>>>();      // 3
    scan_kernel<<<1, 1024>>>();               // 4 (ncu slot, trivial)
    scatter_kernel<<<NPTS / 256, 256>>>();    // 5
    chain_kernel<<<1024, 256>>>(cb);          // 6
    gather_kernel<<<NPTS / GPTS, 256>>>(z, cb, out);  // 7
}

// round 16
// speedup vs baseline: 1.0472x; 1.0472x over previous
#include <cuda_runtime.h>
#include <cstdint>

#define NPTS     32768
#define KCODES   1024
#define DDIM     256
#define HWSZ     1024
#define DHW      (DDIM*HWSZ)
#define HALF_OUT 8388608
#define CMAXC    64
#define PPC      111          // points per pass1 CTA (296 x 111 >= 32768)
#define GRID1    296          // 2 CTAs/SM -> exactly one wave
#define WLCAP    4194304

typedef unsigned int u32;
typedef unsigned short u16;
typedef unsigned long long u64;

// Scratch (static __device__ — no allocations)
__device__ u32    g_c8T[KCODES * 64];   // [8 tile][64 word][128 code] packed int8
__device__ float4 g_cs4[KCODES];        // (cc exact-chain, sc=max|c|, rc=||Δc||, 0)
__device__ float  g_xT[NPTS * DDIM];    // 32MB point-major x copy
__device__ float  g_xx[NPTS];
__device__ float  g_mar[NPTS];
__device__ float  g_minq[NPTS];
__device__ u16    g_cand[NPTS * CMAXC];
__device__ float  g_cdda[NPTS * CMAXC];
__device__ u32    g_ccnt[NPTS];
__device__ u32    g_wl[WLCAP];          // worklist: (n<<10)|k  (multi-cand pts only)
__device__ u32    g_wcnt;
__device__ u64    g_best[NPTS];

__device__ __forceinline__ u32 smem_u32(const void* p) {
    return (u32)__cvta_generic_to_shared(p);
}
__device__ __forceinline__ void cp_async16(u32 dst, const void* src) {
    asm volatile("cp.async.cg.shared.global [%0], [%1], 16;" :: "r"(dst), "l"(src));
}
__device__ __forceinline__ void cp_commit() { asm volatile("cp.async.commit_group;"); }
__device__ __forceinline__ void cp_wait0()  { asm volatile("cp.async.wait_group 0;" ::: "memory"); }

// ---------------------------------------------------------------------------
// code_prep: one WARP per code (6.2us). Zeroes worklist counter.
// ---------------------------------------------------------------------------
__global__ void code_prep(const float* __restrict__ cb) {
    const int tid = threadIdx.x, lane = tid & 31, wid = tid >> 5;
    if (blockIdx.x == 0 && tid == 0) g_wcnt = 0;
    const int k = blockIdx.x * 8 + wid;
    const float* row = cb + (size_t)k * DDIM;

    float4 va = *(const float4*)(row + lane * 8);
    float4 vb = *(const float4*)(row + lane * 8 + 4);
    float mx = fmaxf(fmaxf(fmaxf(fabsf(va.x), fabsf(va.y)), fmaxf(fabsf(va.z), fabsf(va.w))),
                     fmaxf(fmaxf(fabsf(vb.x), fabsf(vb.y)), fmaxf(fabsf(vb.z), fabsf(vb.w))));
    #pragma unroll
    for (int o = 16; o; o >>= 1) mx = fmaxf(mx, __shfl_xor_sync(0xFFFFFFFFu, mx, o));

    float mxx = fmaxf(mx, 1e-30f);
    float s127 = 127.0f / mxx;
    float cinv = mxx / 127.0f;

    float rsum = 0.0f;
    u32 base = (u32)(k >> 7) * 8192u + (u32)(k & 127);
    float vv[8] = {va.x, va.y, va.z, va.w, vb.x, vb.y, vb.z, vb.w};
    #pragma unroll
    for (int h = 0; h < 2; ++h) {
        u32 pk = 0;
        #pragma unroll
        for (int e = 0; e < 4; ++e) {
            float ve = vv[h * 4 + e];
            int q = __float2int_rn(ve * s127);
            q = max(-127, min(127, q));
            float diff = fmaf(-(float)q, cinv, ve);
            rsum += diff * diff;
            pk |= ((u32)(q & 0xFF)) << (8 * e);
        }
        g_c8T[base + (u32)(lane * 2 + h) * 128u] = pk;
    }
    #pragma unroll
    for (int o = 16; o; o >>= 1) rsum += __shfl_xor_sync(0xFFFFFFFFu, rsum, o);

    if (lane == 0) {
        float s = 0.0f;
        for (int d0 = 0; d0 < DDIM; d0 += 16) {
            float4 w0 = *(const float4*)(row + d0);
            float4 w1 = *(const float4*)(row + d0 + 4);
            float4 w2 = *(const float4*)(row + d0 + 8);
            float4 w3 = *(const float4*)(row + d0 + 12);
            float v[16] = {w0.x, w0.y, w0.z, w0.w, w1.x, w1.y, w1.z, w1.w,
                           w2.x, w2.y, w2.z, w2.w, w3.x, w3.y, w3.z, w3.w};
            #pragma unroll
            for (int e = 0; e < 16; ++e)
                s = __fadd_rn(s, __fmul_rn(v[e], v[e]));
        }
        g_cs4[k] = make_float4(s, mx, sqrtf(rsum) * 1.02f + 1e-7f, 0.0f);
    }
}

// ---------------------------------------------------------------------------
// Pass 1: fused x-prep (+xT copy) + dp4a GEMM + certified-margin collect.
// ---------------------------------------------------------------------------
__global__ void __launch_bounds__(512, 2)
pass1_kernel(const float* __restrict__ z) {
    extern __shared__ u32 sdyn[];   // As[8192] | Bs0[8192] | Bs1[8192] | sCS[2048]
    u32* As = sdyn;
    u32* Bsb[2] = { sdyn + 8192, sdyn + 16384 };
    float2* sCS = (float2*)(sdyn + 24576);
    __shared__ float sMar[128], sXX[128], sSX[128], sRX[128];
    __shared__ float sred[2][16];

    const int tid = threadIdx.x;
    const int tx = tid & 31;
    const int ty = tid >> 5;
    const int p0 = blockIdx.x * PPC;
    const int npts = min(PPC, NPTS - p0);

    {
        u32 db = smem_u32(Bsb[0]);
        #pragma unroll
        for (int r = 0; r < 4; ++r)
            cp_async16(db + (u32)(r * 512 + tid) * 16u, g_c8T + (r * 512 + tid) * 4);
        cp_commit();
    }

    {
        float mcc = 0.0f, mrc = 0.0f;
        #pragma unroll
        for (int l = 0; l < 2; ++l) {
            int k = tid + l * 512;
            float4 cs = g_cs4[k];
            sCS[k] = make_float2(cs.x, cs.y);
            mcc = fmaxf(mcc, cs.x);
            mrc = fmaxf(mrc, cs.z);
        }
        #pragma unroll
        for (int o = 16; o; o >>= 1) {
            mcc = fmaxf(mcc, __shfl_xor_sync(0xFFFFFFFFu, mcc, o));
            mrc = fmaxf(mrc, __shfl_xor_sync(0xFFFFFFFFu, mrc, o));
        }
        if (tx == 0) { sred[0][ty] = mcc; sred[1][ty] = mrc; }
    }

    // x-prep: threads 0-127 pinned xx chains; 128-255 pack + residual + xT.
    if (tid < 128) {
        const int p = tid, n = p0 + p;
        if (p < npts) {
            const int bb = n >> 10, hw = n & 1023;
            const float* bp = z + (size_t)bb * DHW + hw;
            g_ccnt[n] = 0;
            float s = 0.0f;
            for (int d0 = 0; d0 < DDIM; d0 += 16) {
                float v[16];
                #pragma unroll
                for (int e = 0; e < 16; ++e) v[e] = bp[(size_t)(d0 + e) * HWSZ];
                #pragma unroll
                for (int e = 0; e < 16; ++e)
                    s = __fadd_rn(s, __fmul_rn(v[e], v[e]));
            }
            g_xx[n] = s;
            sXX[p] = s;
        } else {
            sXX[p] = 3.0e38f;
        }
    } else if (tid < 256) {
        const int p = tid - 128, n = p0 + p;
        if (p < npts) {
            const int bb = n >> 10, hw = n & 1023;
            const float* bp = z + (size_t)bb * DHW + hw;
            float mx = 0.0f;
            for (int d0 = 0; d0 < DDIM; d0 += 16) {
                float v[16];
                #pragma unroll
                for (int e = 0; e < 16; ++e) v[e] = bp[(size_t)(d0 + e) * HWSZ];
                #pragma unroll
                for (int e = 0; e < 16; ++e) mx = fmaxf(mx, fabsf(v[e]));
            }
            float mxx = fmaxf(mx, 1e-30f);
            float s127 = 127.0f / mxx;
            float xinv = mxx / 127.0f;
            float rsum = 0.0f;
            float* xtr = g_xT + (size_t)n * DDIM;
            #pragma unroll 4
            for (int w = 0; w < 64; ++w) {
                u32 pk = 0;
                float xe4[4];
                #pragma unroll
                for (int e = 0; e < 4; ++e) {
                    float xe = bp[(size_t)(w * 4 + e) * HWSZ];   // L2 hit
                    xe4[e] = xe;
                    int q = __float2int_rn(xe * s127);
                    q = max(-127, min(127, q));
                    float diff = fmaf(-(float)q, xinv, xe);
                    rsum += diff * diff;
                    pk |= ((u32)(q & 0xFF)) << (8 * e);
                }
                As[w * 128 + p] = pk;
                float4 xv; xv.x = xe4[0]; xv.y = xe4[1]; xv.z = xe4[2]; xv.w = xe4[3];
                *(float4*)(xtr + w * 4) = xv;
            }
            sSX[p] = mx * (1.0f / 16129.0f);
            sRX[p] = sqrtf(rsum) * 1.02f + 1e-7f;
        } else {
            #pragma unroll 8
            for (int w = 0; w < 64; ++w) As[w * 128 + p] = 0u;
            sSX[p] = 0.0f;
            sRX[p] = 0.0f;
        }
    }
    __syncthreads();

    float MCC = 0.0f, MRC = 0.0f;
    #pragma unroll
    for (int i = 0; i < 16; ++i) {
        MCC = fmaxf(MCC, sred[0][i]);
        MRC = fmaxf(MRC, sred[1][i]);
    }
    const float Smax = sqrtf(MCC);

    if (tid < 128) {
        const int p = tid;
        if (p < npts) {
            float rx = sRX[p], s = sXX[p];
            float errdot = rx * Smax + (sqrtf(s) + rx) * MRC;
            float marg = 2.5f * errdot + 2e-4f;
            sMar[p] = marg;
            g_mar[p0 + p] = marg;
        } else {
            sMar[p] = 0.0f;
        }
    }
    cp_wait0();
    __syncthreads();

    float gmin8[8];
    #pragma unroll
    for (int i = 0; i < 8; ++i) gmin8[i] = 3.0e38f;

    for (int t = 0; t < 8; ++t) {
        if (t < 7) {
            u32 db = smem_u32(Bsb[(t + 1) & 1]);
            const u32* src = g_c8T + (t + 1) * 8192;
            #pragma unroll
            for (int r = 0; r < 4; ++r)
                cp_async16(db + (u32)(r * 512 + tid) * 16u, src + (r * 512 + tid) * 4);
            cp_commit();
        }
        const uint4* Bt4 = (const uint4*)Bsb[t & 1];
        const uint4* At4 = (const uint4*)As;

        int m[32];
        #pragma unroll
        for (int i = 0; i < 32; ++i) m[i] = 0;

        #pragma unroll 4
        for (int w = 0; w < 64; ++w) {
            uint4 A0 = At4[w * 32 + ty * 2];
            uint4 A1 = At4[w * 32 + ty * 2 + 1];
            uint4 B  = Bt4[w * 32 + tx];
            int a[8] = {(int)A0.x, (int)A0.y, (int)A0.z, (int)A0.w,
                        (int)A1.x, (int)A1.y, (int)A1.z, (int)A1.w};
            int bb[4] = {(int)B.x, (int)B.y, (int)B.z, (int)B.w};
            #pragma unroll
            for (int i = 0; i < 8; ++i)
                #pragma unroll
                for (int j = 0; j < 4; ++j)
                    m[i * 4 + j] = __dp4a(a[i], bb[j], m[i * 4 + j]);
        }

        {
            float xx8[8], sx8[8], lmin8[8];
            #pragma unroll
            for (int i = 0; i < 8; ++i) {
                xx8[i] = sXX[ty * 8 + i];
                sx8[i] = sSX[ty * 8 + i];
                lmin8[i] = 3.0e38f;
            }
            #pragma unroll
            for (int j = 0; j < 4; ++j) {
                float2 cj = sCS[t * 128 + tx * 4 + j];
                #pragma unroll
                for (int i = 0; i < 8; ++i) {
                    float dd = fmaf(-2.0f * sx8[i] * cj.y,
                                    (float)m[i * 4 + j], xx8[i] + cj.x);
                    m[i * 4 + j] = __float_as_int(dd);
                    lmin8[i] = fminf(lmin8[i], dd);
                }
            }
            #pragma unroll
            for (int i = 0; i < 8; ++i) {
                float v = lmin8[i];
                #pragma unroll
                for (int o = 1; o < 32; o <<= 1)
                    v = fminf(v, __shfl_xor_sync(0xFFFFFFFFu, v, o));
                gmin8[i] = fminf(gmin8[i], v);
            }
            #pragma unroll
            for (int i = 0; i < 8; ++i) {
                int pt = ty * 8 + i;
                if (pt < npts) {
                    float thr = gmin8[i] + sMar[pt];
                    int n = p0 + pt;
                    #pragma unroll
                    for (int j = 0; j < 4; ++j) {
                        float dd = __int_as_float(m[i * 4 + j]);
                        if (dd <= thr) {
                            u32 s = atomicAdd(&g_ccnt[n], 1u);
                            if (s < CMAXC) {
                                g_cand[(size_t)n * CMAXC + s] = (u16)(t * 128 + tx * 4 + j);
                                g_cdda[(size_t)n * CMAXC + s] = dd;
                            }
                        }
                    }
                }
            }
        }
        if (t < 7) cp_wait0();
        __syncthreads();
    }
    if (tx == 0) {
        #pragma unroll
        for (int i = 0; i < 8; ++i) {
            int pt = ty * 8 + i;
            if (pt < npts) g_minq[p0 + pt] = gmin8[i];
        }
    }
}

// ---------------------------------------------------------------------------
// filter: per point. Final-window survivors: ONE survivor -> it IS the argmin
// (window is a certified superset of {argmin}; ties force >=2 survivors) ->
// write g_best directly, no exact work. Multi -> push to global worklist.
// ---------------------------------------------------------------------------
__global__ void __launch_bounds__(256)
filter_kernel() {
    int n = blockIdx.x * 256 + threadIdx.x;
    u32 cnt = g_ccnt[n];
    if (cnt <= CMAXC) {
        float thr = g_minq[n] + g_mar[n];
        u32 loc[CMAXC];
        int nl = 0;
        for (u32 c = 0; c < cnt; ++c) {
            if (g_cdda[(size_t)n * CMAXC + c] <= thr)
                loc[nl++] = (u32)g_cand[(size_t)n * CMAXC + c];
        }
        if (nl == 1) {
            g_best[n] = (u64)loc[0];            // singleton: certified argmin
        } else if (nl >= 2) {
            g_best[n] = ~0ull;
            u32 base = atomicAdd(&g_wcnt, (u32)nl);
            for (int i = 0; i < nl && base + i < WLCAP; ++i)
                g_wl[base + i] = ((u32)n << 10) | loc[i];
        } else {                                 // defensive: never happens
            g_best[n] = ~0ull;
            u32 base = atomicAdd(&g_wcnt, 1024u);
            for (int k = 0; k < 1024 && base + k < WLCAP; ++k)
                g_wl[base + k] = ((u32)n << 10) | (u32)k;
        }
    } else {                                     // overflow: full exact scan
        g_best[n] = ~0ull;
        u32 base = atomicAdd(&g_wcnt, 1024u);
        for (int k = 0; k < 1024 && base + k < WLCAP; ++k)
            g_wl[base + k] = ((u32)n << 10) | (u32)k;
    }
}

// ---------------------------------------------------------------------------
// chain: exact pinned bitwise chains for multi-candidate points only.
// Winner via atomicMin on (dd_bits<<32)|k  (lexicographic = jnp.argmin).
// ---------------------------------------------------------------------------
__global__ void __launch_bounds__(256)
chain_kernel(const float* __restrict__ cb) {
    u32 W = g_wcnt;
    if (W > WLCAP) W = WLCAP;
    for (u32 i = blockIdx.x * 256 + threadIdx.x; i < W; i += gridDim.x * 256) {
        u32 e = g_wl[i];
        u32 n = e >> 10;
        u32 k = e & 1023u;
        const float4* xr = (const float4*)(g_xT + (size_t)n * DDIM);
        const float4* cr = (const float4*)(cb + (size_t)k * DDIM);
        float mm = 0.0f;
        #pragma unroll 8
        for (int d4 = 0; d4 < DDIM / 4; ++d4) {
            float4 xv = xr[d4];
            float4 cv = cr[d4];
            mm = __fmaf_rn(xv.x, cv.x, mm);
            mm = __fmaf_rn(xv.y, cv.y, mm);
            mm = __fmaf_rn(xv.z, cv.z, mm);
            mm = __fmaf_rn(xv.w, cv.w, mm);
        }
        float t1 = __fadd_rn(g_xx[n], g_cs4[k].x);
        float dd = __fadd_rn(t1, -(2.0f * mm));
        u64 pack = ((u64)(u32)__float_as_int(dd) << 32) | k;
        atomicMin(&g_best[n], pack);
    }
}

// ---------------------------------------------------------------------------
// Gather + straight-through outputs (proven form, ~19.5us).
// ---------------------------------------------------------------------------
#define GPTS 32
__global__ void __launch_bounds__(256)
gather_kernel(const float* __restrict__ z, const float* __restrict__ cb,
              float* __restrict__ out) {
    __shared__ float tile[GPTS][DDIM + 1];
    __shared__ int sidx[GPTS];

    const int tid = threadIdx.x;
    const int p0 = blockIdx.x * GPTS;
    const int b = p0 >> 10;
    const int hw0 = p0 & 1023;

    if (tid < GPTS) sidx[tid] = (int)(g_best[p0 + tid] & 1023u);
    __syncthreads();

    #pragma unroll
    for (int r = 0; r < 8; ++r) {
        int lin = tid + r * 256;
        int p = lin >> 6;
        int d4 = (lin & 63) << 2;
        float4 v = *reinterpret_cast<const float4*>(cb + (size_t)sidx[p] * DDIM + d4);
        tile[p][d4 + 0] = v.x;
        tile[p][d4 + 1] = v.y;
        tile[p][d4 + 2] = v.z;
        tile[p][d4 + 3] = v.w;
    }
    __syncthreads();

    const float* zb = z + (size_t)b * DHW + hw0;
    float* o1 = out + (size_t)b * DHW + hw0;
    const int p = tid & 31;
    const int dchunk = tid >> 5;

    #pragma unroll
    for (int dd = 0; dd < DDIM; dd += 8) {
        int d = dd + dchunk;
        size_t off = (size_t)d * HWSZ + p;
        float x = zb[off];
        float q = tile[p][d];
        float t = __fadd_rn(q, -x);
        o1[off]            = __fadd_rn(x, t);
        o1[off + HALF_OUT] = q;
    }
}

// ---------------------------------------------------------------------------
extern "C" void kernel_launch(void* const* d_in, const int* in_sizes, int n_in,
                              void* d_out, int out_size) {
    const float* z  = (const float*)d_in[0];   // z_e_x  [32,256,32,32]
    const float* cb = (const float*)d_in[1];   // codebook [1024,256]
    float* out = (float*)d_out;                // [2, 32,256,32,32]

    static int inited = 0;
    if (!inited) {
        cudaFuncSetAttribute(pass1_kernel,
                             cudaFuncAttributeMaxDynamicSharedMemorySize, 106496);
        inited = 1;
    }

    code_prep<<<128, 256>>>(cb);              // 1 (also zeroes g_wcnt)
    pass1_kernel<<<GRID1, 512, 106496>>>(z);  // 2
    filter_kernel<<<NPTS / 256, 256>>>();     // 3
    chain_kernel<<<1024, 256>>>(cb);          // 4 (ncu slot)
    gather_kernel<<<NPTS / GPTS, 256>>>(z, cb, out);  // 5
}